// round 2
// baseline (speedup 1.0000x reference)
#include <cuda_runtime.h>
#include <stdint.h>

#define HH 1024
#define WW 2048
#define HW (HH * WW)              // 2,097,152 pixels
#define NI 128                    // instances
#define NB 10                     // "thing" classes 24..33
#define NBINS (NI * NB)           // 1280
#define THREADS 256
#define NGRP (HW / 4)             // 524,288 four-pixel groups
#define NBLK (NGRP / THREADS)     // 2048 blocks

// Scratch (no cudaMalloc allowed). Zero-initialized at module load; the
// last-finishing block re-zeroes them at the end of every run, so every
// graph replay starts from a clean state (deterministic).
__device__ int          g_counts[NBINS];
__device__ float        g_sums[NBINS];
__device__ unsigned int g_done;

// ---------------------------------------------------------------------------
// Single fused kernel:
//   per 4-pixel group (one thread):
//     - inst = (24 <= seg <= 33) ? instance_maps : 0
//     - shared-mem histogram: counts[(inst-1)][seg-24]
//     - shared-mem prob sums over the 10 "thing" channels (loaded only if
//       any of the 4 pixels is a thing; ~75% of groups)
//     - write ALL 128 mask channels directly (final values, no pre-zero
//       pass): 128 coalesced float4 streaming stores = the DRAM-write-bound
//       part, under which the reads above hide.
//   per block: flush shared bins to global with RED atomics.
//   last block (ticket counter): finalize the 5 tail outputs, then reset
//   the scratch bins + counter for the next replay.
// ---------------------------------------------------------------------------
__global__ void __launch_bounds__(THREADS)
fused_kernel(const int4*   __restrict__ seg4,
             const int4*   __restrict__ inst4,
             const float4* __restrict__ probs4,
             const float*  __restrict__ inst_probs,
             float*        __restrict__ out) {
    __shared__ int          s_cnt[NBINS];
    __shared__ float        s_sum[NBINS];
    __shared__ unsigned int s_ticket;

    const int tid = threadIdx.x;
    for (int i = tid; i < NBINS; i += THREADS) { s_cnt[i] = 0; s_sum[i] = 0.0f; }
    __syncthreads();

    const int t = blockIdx.x * THREADS + tid;       // 4-pixel group index

    const int4 sg = seg4[t];
    const int4 im = inst4[t];
    const int ss[4] = { sg.x, sg.y, sg.z, sg.w };
    const int iv[4] = { im.x, im.y, im.z, im.w };
    int ii[4];

    #pragma unroll
    for (int j = 0; j < 4; ++j) {
        const int s = ss[j];
        const int inst = (s >= 24 && s <= 33) ? iv[j] : 0;
        ii[j] = inst;
        if (inst > 0)
            atomicAdd(&s_cnt[(inst - 1) * NB + (s - 24)], 1);
    }

    const int any = ii[0] | ii[1] | ii[2] | ii[3];

    if (any) {
        #pragma unroll
        for (int c = 0; c < NB; ++c) {
            const float4 pv = __ldg(&probs4[(size_t)(24 + c) * NGRP + t]);
            const float pa[4] = { pv.x, pv.y, pv.z, pv.w };
            #pragma unroll
            for (int j = 0; j < 4; ++j)
                if (ii[j] > 0)
                    atomicAdd(&s_sum[(ii[j] - 1) * NB + c], pa[j]);
        }
    }

    // ---- mask writes: 128 channels x float4, streaming stores ----
    float4* out4 = (float4*)out;
    if (!any) {
        const float4 z = make_float4(0.f, 0.f, 0.f, 0.f);
        #pragma unroll 8
        for (int i = 0; i < NI; ++i)
            __stcs(&out4[(size_t)i * NGRP + t], z);
    } else {
        #pragma unroll 4
        for (int i = 0; i < NI; ++i) {
            const int id = i + 1;
            float4 v;
            v.x = (ii[0] == id) ? 1.0f : 0.0f;
            v.y = (ii[1] == id) ? 1.0f : 0.0f;
            v.z = (ii[2] == id) ? 1.0f : 0.0f;
            v.w = (ii[3] == id) ? 1.0f : 0.0f;
            __stcs(&out4[(size_t)i * NGRP + t], v);
        }
    }

    __syncthreads();
    // ---- flush block-local bins (RED, no return) ----
    for (int i = tid; i < NBINS; i += THREADS) {
        const int   cv = s_cnt[i];
        const float sv = s_sum[i];
        if (cv)          atomicAdd(&g_counts[i], cv);
        if (sv != 0.0f)  atomicAdd(&g_sums[i], sv);
    }

    // ---- last-block finalize ----
    __threadfence();                 // make this block's bin flush visible
    __syncthreads();
    if (tid == 0)
        s_ticket = atomicAdd(&g_done, 1u);
    __syncthreads();

    if (s_ticket == (unsigned)(NBLK - 1)) {
        // All other blocks fenced before bumping the counter, so their
        // RED atomics are visible. Read bins via L2 (__ldcg) — never cached
        // in this block's L1.
        if (tid < NI) {
            const int i = tid;
            int tot = 0, best = 0, bestc = 0;
            #pragma unroll
            for (int c = 0; c < NB; ++c) {
                const int v = __ldcg(&g_counts[i * NB + c]);
                tot += v;
                if (v > best) { best = v; bestc = c; }   // first-occurrence ties
            }
            float cls = 0.0f, segp = 0.0f;
            if (tot > 0) {
                cls  = (float)(24 + bestc);
                segp = __ldcg(&g_sums[i * NB + bestc]) / (float)tot;
            }
            float* tail = out + (size_t)NI * HW;
            tail[0 * NI + i] = cls;                 // inst_class
            tail[1 * NI + i] = inst_probs[i];       // instance_probs
            tail[2 * NI + i] = segp;                // seg_prob
            tail[3 * NI + i] = (float)tot;          // total
            tail[4 * NI + i] = (tot > 0) ? 1.0f : 0.0f;  // valid
        }
        __syncthreads();
        // Reset scratch for the next graph replay (kernel-boundary flush
        // makes these plain stores visible to the next launch).
        for (int i = tid; i < NBINS; i += THREADS) {
            g_counts[i] = 0;
            g_sums[i]   = 0.0f;
        }
        if (tid == 0) g_done = 0u;
    }
}

// ---------------------------------------------------------------------------
extern "C" void kernel_launch(void* const* d_in, const int* in_sizes, int n_in,
                              void* d_out, int out_size) {
    const int*   seg    = (const int*)  d_in[0];   // (H, W) int32
    const int*   inst   = (const int*)  d_in[1];   // (H, W) int32
    const float* probs  = (const float*)d_in[2];   // (C, H, W) float32
    const float* iprobs = (const float*)d_in[3];   // (128,) float32
    float* out = (float*)d_out;

    fused_kernel<<<NBLK, THREADS>>>(
        (const int4*)seg, (const int4*)inst, (const float4*)probs, iprobs, out);
}

// round 3
// speedup vs baseline: 2.4260x; 2.4260x over previous
#include <cuda_runtime.h>
#include <stdint.h>

#define HH 1024
#define WW 2048
#define HW (HH * WW)              // 2,097,152 pixels
#define NI 128                    // instances
#define NB 10                     // "thing" classes 24..33
#define NBINS (NI * NB)           // 1280
#define THREADS 256
#define NGRP (HW / 4)             // 524,288 four-pixel groups
#define NBLK_PIX (NGRP / THREADS) // 2048 blocks over pixel groups
#define NBLK_MASK (NBLK_PIX * NI) // 262,144 blocks in the mask kernel

// Scratch (no cudaMalloc allowed). Zero-initialized at load; finalize resets
// the bins + ticket at the end of every run so graph replays are deterministic.
__device__ uint8_t      g_inst8[HW];     // per-pixel instance id (0 = stuff)
__device__ int          g_counts[NBINS];
__device__ float        g_sums[NBINS];
__device__ unsigned int g_done;

// ---------------------------------------------------------------------------
// Kernel 1 (prepass): one sweep over pixels.
//   - inst = (24 <= seg <= 33) ? instance_maps : 0   -> g_inst8 (uchar4 store)
//   - shared-mem histogram counts[(inst-1)][seg-24]
//   - shared-mem prob sums over the 10 "thing" channels (loaded only when one
//     of the thread's 4 pixels is a thing)
//   - RED flush of block bins to global
// ---------------------------------------------------------------------------
__global__ void __launch_bounds__(THREADS)
prepass_kernel(const int4*   __restrict__ seg4,
               const int4*   __restrict__ inst4,
               const float4* __restrict__ probs4) {
    __shared__ int   s_cnt[NBINS];
    __shared__ float s_sum[NBINS];

    const int tid = threadIdx.x;
    for (int i = tid; i < NBINS; i += THREADS) { s_cnt[i] = 0; s_sum[i] = 0.0f; }
    __syncthreads();

    const int t = blockIdx.x * THREADS + tid;       // 4-pixel group index

    const int4 sg = seg4[t];
    const int4 im = inst4[t];
    const int ss[4] = { sg.x, sg.y, sg.z, sg.w };
    const int iv[4] = { im.x, im.y, im.z, im.w };
    int ii[4];

    #pragma unroll
    for (int j = 0; j < 4; ++j) {
        const int s = ss[j];
        const int inst = (s >= 24 && s <= 33) ? iv[j] : 0;
        ii[j] = inst;
        if (inst > 0)
            atomicAdd(&s_cnt[(inst - 1) * NB + (s - 24)], 1);
    }

    // packed per-pixel instance ids (0..128 fit in uint8)
    uchar4 packed;
    packed.x = (uint8_t)ii[0];
    packed.y = (uint8_t)ii[1];
    packed.z = (uint8_t)ii[2];
    packed.w = (uint8_t)ii[3];
    ((uchar4*)g_inst8)[t] = packed;

    if (ii[0] | ii[1] | ii[2] | ii[3]) {
        #pragma unroll
        for (int c = 0; c < NB; ++c) {
            const float4 pv = __ldg(&probs4[(size_t)(24 + c) * NGRP + t]);
            const float pa[4] = { pv.x, pv.y, pv.z, pv.w };
            #pragma unroll
            for (int j = 0; j < 4; ++j)
                if (ii[j] > 0)
                    atomicAdd(&s_sum[(ii[j] - 1) * NB + c], pa[j]);
        }
    }

    __syncthreads();
    for (int i = tid; i < NBINS; i += THREADS) {
        const int   cv = s_cnt[i];
        const float sv = s_sum[i];
        if (cv)          atomicAdd(&g_counts[i], cv);
        if (sv != 0.0f)  atomicAdd(&g_sums[i], sv);
    }
}

// ---------------------------------------------------------------------------
// Kernel 2 (masks): channel-major streaming writes.
//   block b: channel = b / NBLK_PIX, pixel chunk = b % NBLK_PIX.
//   Each thread reads 4 instance ids (uchar4, L2-resident 2MB array) and
//   writes one float4 of the one-hot mask with a streaming store. All of a
//   block's stores land in a contiguous 16KB region -> page-local, unlike R2.
//   The globally-last block (ticket) finalizes the 5 tail outputs and resets
//   the scratch state for the next graph replay.
// ---------------------------------------------------------------------------
__global__ void __launch_bounds__(THREADS)
mask_kernel(const float* __restrict__ inst_probs,
            float*       __restrict__ out) {
    const int tid  = threadIdx.x;
    const int chan = blockIdx.x / NBLK_PIX;               // 0..127
    const int t    = (blockIdx.x % NBLK_PIX) * THREADS + tid;  // group index

    const uchar4 p  = ((const uchar4*)g_inst8)[t];
    const int    id = chan + 1;

    float4 v;
    v.x = (p.x == id) ? 1.0f : 0.0f;
    v.y = (p.y == id) ? 1.0f : 0.0f;
    v.z = (p.z == id) ? 1.0f : 0.0f;
    v.w = (p.w == id) ? 1.0f : 0.0f;
    __stcs(&((float4*)out)[(size_t)chan * NGRP + t], v);

    // ---- last-block finalize (bins were completed by the prepass kernel,
    //      which finished before this kernel launched) ----
    __shared__ unsigned int s_ticket;
    __syncthreads();
    if (tid == 0)
        s_ticket = atomicAdd(&g_done, 1u);
    __syncthreads();

    if (s_ticket == (unsigned)(NBLK_MASK - 1)) {
        if (tid < NI) {
            const int i = tid;
            int tot = 0, best = 0, bestc = 0;
            #pragma unroll
            for (int c = 0; c < NB; ++c) {
                const int v2 = g_counts[i * NB + c];
                tot += v2;
                if (v2 > best) { best = v2; bestc = c; }  // first-occurrence ties
            }
            float cls = 0.0f, segp = 0.0f;
            if (tot > 0) {
                cls  = (float)(24 + bestc);
                segp = g_sums[i * NB + bestc] / (float)tot;
            }
            float* tail = out + (size_t)NI * HW;
            tail[0 * NI + i] = cls;                      // inst_class
            tail[1 * NI + i] = inst_probs[i];            // instance_probs
            tail[2 * NI + i] = segp;                     // seg_prob
            tail[3 * NI + i] = (float)tot;               // total
            tail[4 * NI + i] = (tot > 0) ? 1.0f : 0.0f;  // valid
        }
        __syncthreads();
        // Reset scratch for the next graph replay.
        for (int i = tid; i < NBINS; i += THREADS) {
            g_counts[i] = 0;
            g_sums[i]   = 0.0f;
        }
        if (tid == 0) g_done = 0u;
    }
}

// ---------------------------------------------------------------------------
extern "C" void kernel_launch(void* const* d_in, const int* in_sizes, int n_in,
                              void* d_out, int out_size) {
    const int*   seg    = (const int*)  d_in[0];   // (H, W) int32
    const int*   inst   = (const int*)  d_in[1];   // (H, W) int32
    const float* probs  = (const float*)d_in[2];   // (C, H, W) float32
    const float* iprobs = (const float*)d_in[3];   // (128,) float32
    float* out = (float*)d_out;

    prepass_kernel<<<NBLK_PIX, THREADS>>>(
        (const int4*)seg, (const int4*)inst, (const float4*)probs);
    mask_kernel<<<NBLK_MASK, THREADS>>>(iprobs, out);
}

// round 4
// speedup vs baseline: 3.4258x; 1.4121x over previous
#include <cuda_runtime.h>
#include <stdint.h>

#define HH 1024
#define WW 2048
#define HW (HH * WW)              // 2,097,152 pixels
#define NI 128                    // instances
#define NB 10                     // "thing" classes 24..33
#define NBINS (NI * NB)           // 1280
#define THREADS 256
#define NGRP (HW / 4)             // 524,288 four-pixel groups
#define NBLK_STATS (NGRP / THREADS)            // 2048 stats blocks
#define NQ ((size_t)NI * HW / 4)               // float4 count of mask region
#define NBLK_ZERO ((int)(NQ / THREADS))        // 262,144 zero-fill blocks
#define NBLK_A (NBLK_STATS + NBLK_ZERO)

// Scratch (no cudaMalloc allowed). Bins are reset by kernel B's finalize
// block every run; g_inst8 is fully rewritten every run. Deterministic
// across graph replays.
__device__ uint8_t g_inst8[HW];      // per-pixel instance id (0 = stuff)
__device__ int     g_counts[NBINS];
__device__ float   g_sums[NBINS];

// ---------------------------------------------------------------------------
// Kernel A: fused zero-fill + stats.
//   blocks [0, 2048): stats prepass
//     - inst = (24 <= seg <= 33) ? instance_maps : 0  -> g_inst8 (uchar4)
//     - shared-mem histogram counts[(inst-1)][seg-24]
//     - shared-mem prob sums over the 10 thing channels (loaded only when a
//       thread's 4 pixels contain a thing) ; RED flush to global bins
//   blocks [2048, NBLK_A): pure float4 streaming zero-fill of the mask
//     region (dependency-free stores -> rides the DRAM write roofline).
//   The stats blocks schedule in wave 1, so their ~76 MB of reads hide under
//   the 1.073 GB write stream.
// ---------------------------------------------------------------------------
__global__ void __launch_bounds__(THREADS)
fill_stats_kernel(const int4*   __restrict__ seg4,
                  const int4*   __restrict__ inst4,
                  const float4* __restrict__ probs4,
                  float4*       __restrict__ out4) {
    const int tid = threadIdx.x;
    const int b   = blockIdx.x;

    if (b >= NBLK_STATS) {
        // ---------------- zero-fill path (pure streaming stores) ----------
        const size_t i = (size_t)(b - NBLK_STATS) * THREADS + tid;
        __stcs(&out4[i], make_float4(0.f, 0.f, 0.f, 0.f));
        return;
    }

    // -------------------- stats path ------------------------------------
    __shared__ int   s_cnt[NBINS];
    __shared__ float s_sum[NBINS];
    for (int i = tid; i < NBINS; i += THREADS) { s_cnt[i] = 0; s_sum[i] = 0.0f; }
    __syncthreads();

    const int t = b * THREADS + tid;                // 4-pixel group index

    const int4 sg = seg4[t];
    const int4 im = inst4[t];
    const int ss[4] = { sg.x, sg.y, sg.z, sg.w };
    const int iv[4] = { im.x, im.y, im.z, im.w };
    int ii[4];

    #pragma unroll
    for (int j = 0; j < 4; ++j) {
        const int s = ss[j];
        const int inst = (s >= 24 && s <= 33) ? iv[j] : 0;
        ii[j] = inst;
        if (inst > 0)
            atomicAdd(&s_cnt[(inst - 1) * NB + (s - 24)], 1);
    }

    uchar4 packed;
    packed.x = (uint8_t)ii[0];
    packed.y = (uint8_t)ii[1];
    packed.z = (uint8_t)ii[2];
    packed.w = (uint8_t)ii[3];
    ((uchar4*)g_inst8)[t] = packed;

    if (ii[0] | ii[1] | ii[2] | ii[3]) {
        #pragma unroll
        for (int c = 0; c < NB; ++c) {
            const float4 pv = __ldg(&probs4[(size_t)(24 + c) * NGRP + t]);
            const float pa[4] = { pv.x, pv.y, pv.z, pv.w };
            #pragma unroll
            for (int j = 0; j < 4; ++j)
                if (ii[j] > 0)
                    atomicAdd(&s_sum[(ii[j] - 1) * NB + c], pa[j]);
        }
    }

    __syncthreads();
    for (int i = tid; i < NBINS; i += THREADS) {
        const int   cv = s_cnt[i];
        const float sv = s_sum[i];
        if (cv)          atomicAdd(&g_counts[i], cv);
        if (sv != 0.0f)  atomicAdd(&g_sums[i], sv);
    }
}

// ---------------------------------------------------------------------------
// Kernel B: sparse scatter of the 1.0f entries + finalize.
//   blocks [0, 2048): each thread reads 4 instance ids (uchar4 from the
//     L2-hot 2MB g_inst8) and stores 1.0f into out[(inst-1)*HW + p] for the
//     ~0.23%*4 positions that are things. ~617K scattered 4B stores ≈ 20MB
//     of dirty sectors.
//   block 2048: computes the 5 tail outputs from the completed bins (kernel
//     boundary after A guarantees completeness), then resets the bins for
//     the next graph replay. No tickets/fences needed.
// ---------------------------------------------------------------------------
__global__ void __launch_bounds__(THREADS)
scatter_finalize_kernel(const float* __restrict__ inst_probs,
                        float*       __restrict__ out) {
    const int tid = threadIdx.x;
    const int b   = blockIdx.x;

    if (b < NBLK_STATS) {
        const int t  = b * THREADS + tid;           // 4-pixel group index
        const int p0 = t * 4;
        const uchar4 p = ((const uchar4*)g_inst8)[t];
        const int ii[4] = { p.x, p.y, p.z, p.w };
        #pragma unroll
        for (int j = 0; j < 4; ++j)
            if (ii[j] > 0)
                out[(size_t)(ii[j] - 1) * HW + p0 + j] = 1.0f;
        return;
    }

    // ---- finalize block ----
    if (tid < NI) {
        const int i = tid;
        int tot = 0, best = 0, bestc = 0;
        #pragma unroll
        for (int c = 0; c < NB; ++c) {
            const int v = g_counts[i * NB + c];
            tot += v;
            if (v > best) { best = v; bestc = c; }   // first-occurrence ties
        }
        float cls = 0.0f, segp = 0.0f;
        if (tot > 0) {
            cls  = (float)(24 + bestc);
            segp = g_sums[i * NB + bestc] / (float)tot;
        }
        float* tail = out + (size_t)NI * HW;
        tail[0 * NI + i] = cls;                      // inst_class
        tail[1 * NI + i] = inst_probs[i];            // instance_probs
        tail[2 * NI + i] = segp;                     // seg_prob
        tail[3 * NI + i] = (float)tot;               // total
        tail[4 * NI + i] = (tot > 0) ? 1.0f : 0.0f;  // valid
    }
    __syncthreads();
    // Reset scratch bins for the next graph replay.
    for (int i = tid; i < NBINS; i += THREADS) {
        g_counts[i] = 0;
        g_sums[i]   = 0.0f;
    }
}

// ---------------------------------------------------------------------------
extern "C" void kernel_launch(void* const* d_in, const int* in_sizes, int n_in,
                              void* d_out, int out_size) {
    const int*   seg    = (const int*)  d_in[0];   // (H, W) int32
    const int*   inst   = (const int*)  d_in[1];   // (H, W) int32
    const float* probs  = (const float*)d_in[2];   // (C, H, W) float32
    const float* iprobs = (const float*)d_in[3];   // (128,) float32
    float* out = (float*)d_out;

    fill_stats_kernel<<<NBLK_A, THREADS>>>(
        (const int4*)seg, (const int4*)inst, (const float4*)probs,
        (float4*)out);
    scatter_finalize_kernel<<<NBLK_STATS + 1, THREADS>>>(iprobs, out);
}